// round 1
// baseline (speedup 1.0000x reference)
#include <cuda_runtime.h>
#include <math.h>

// ---------------- problem constants ----------------
#define NS   4
#define BT   10      // B*T = 2*5
#define C    384
#define CTXC 128
#define DH   64
#define TI   64      // tokens per attn block
#define MAXBLK 100   // max token-tiles per (stage,b)  (stage0: 6400/64)
#define PSTRIDE 386  // per-partial: m, Z, wx[384]
#define SCALE 0.125f // 64^-0.5

// ---------------- scratch (static device globals, allowed) ----------------
__device__ float g_wsim  [NS*BT*C];
__device__ float g_outvec[NS*BT*C];
__device__ float g_part  [NS*BT*MAXBLK*PSTRIDE];

__constant__ int c_nblk[NS] = {100, 25, 7, 2};

// ================= K1: per-(stage,b) tiny projections =================
// a    = Wp @ audio + bp                          (384)
// cqk  = Wcqk @ (a + pe[b%5])                     (64)
// cv   = Wcv  @ a                                 (64)
// wsim = SCALE * Wqk^T @ cqk                      (384)
// outvec = Wo @ cv + bo                           (384)   [vout row value]
__global__ void k_prep(const float* __restrict__ a0, const float* __restrict__ a1,
                       const float* __restrict__ a2, const float* __restrict__ a3,
                       const float* __restrict__ Wp, const float* __restrict__ bp,
                       const float* __restrict__ pe,
                       const float* __restrict__ Wqk, const float* __restrict__ Wcqk,
                       const float* __restrict__ Wcv,
                       const float* __restrict__ Wo,  const float* __restrict__ bo)
{
    int b = blockIdx.x, s = blockIdx.y, tid = threadIdx.x;
    __shared__ float ash[CTXC];
    __shared__ float a_sh[C], apc_sh[C];
    __shared__ float cqk_sh[DH], cv_sh[DH];

    const float* au = (s==0 ? a0 : s==1 ? a1 : s==2 ? a2 : a3) + b*CTXC;
    if (tid < CTXC) ash[tid] = au[tid];
    __syncthreads();

    {
        const float* w = Wp + ((size_t)s*C + tid)*CTXC;
        float acc = bp[s*C + tid];
        #pragma unroll 8
        for (int k = 0; k < CTXC; k++) acc += w[k]*ash[k];
        a_sh[tid]   = acc;
        apc_sh[tid] = acc + pe[((size_t)s*5 + (b%5))*C + tid];
    }
    __syncthreads();

    if (tid < DH) {
        const float* w1 = Wcqk + ((size_t)s*DH + tid)*C;
        const float* w2 = Wcv  + ((size_t)s*DH + tid)*C;
        float q = 0.f, v = 0.f;
        #pragma unroll 8
        for (int c = 0; c < C; c++) { q += w1[c]*apc_sh[c]; v += w2[c]*a_sh[c]; }
        cqk_sh[tid] = q; cv_sh[tid] = v;
    }
    __syncthreads();

    float ws = 0.f;
    float ov = bo[s*C + tid];
    #pragma unroll
    for (int d = 0; d < DH; d++) {
        ws += Wqk[((size_t)s*DH + d)*C + tid] * cqk_sh[d];   // coalesced over tid
        ov += Wo [((size_t)s*C + tid)*DH + d] * cv_sh[d];
    }
    g_wsim  [((size_t)s*BT + b)*C + tid] = ws * SCALE;
    g_outvec[((size_t)s*BT + b)*C + tid] = ov;
}

// ================= K2: streaming sim + block-local softmax partials =================
// One block = 64 tokens of one (b). 256 threads = 4 channel-rows x 64 tokens.
// Pass 1: read fmap+pos coalesced per channel row, accumulate s_i, stash fmap tile
//         in padded shared (stride 65 -> bank-conflict-free in pass 2).
// Pass 2: local softmax (m, Z) over the 64 tokens, weighted fmap sum wx[384].
// Emit (m, Z, wx) partial per block; global merge happens in k_combine.
extern __shared__ float tileF[];   // C * 65 floats = 99,840 B

__global__ void k_attn(const float* __restrict__ fmap, const float* __restrict__ pos,
                       int hw, int stage)
{
    __shared__ float wsh[C];
    __shared__ float sred[256];
    __shared__ float s_sh[TI];
    __shared__ float p_sh[TI];
    __shared__ float red_m, red_z;

    int tid   = threadIdx.x;
    int b     = blockIdx.y;
    int blk   = blockIdx.x;
    int iBase = blk * TI;
    int c_off = tid >> 6;      // 0..3
    int i     = tid & 63;
    int token = iBase + i;
    bool valid = token < hw;

    for (int c = tid; c < C; c += 256)
        wsh[c] = g_wsim[((size_t)stage*BT + b)*C + c];
    __syncthreads();

    float acc = 0.f;
    const float* fb = fmap + (size_t)b*C*hw + token;
    const float* pb = pos  + (size_t)b*C*hw + token;
    if (valid) {
        #pragma unroll 8
        for (int cB = 0; cB < C; cB += 4) {
            int c = cB + c_off;
            size_t off = (size_t)c * hw;
            float f = __ldg(fb + off);
            float p = __ldg(pb + off);
            tileF[c*65 + i] = f;
            acc += (f + p) * wsh[c];
        }
    } else {
        #pragma unroll 8
        for (int cB = 0; cB < C; cB += 4) tileF[(cB + c_off)*65 + i] = 0.f;
    }
    sred[tid] = acc;
    __syncthreads();

    if (tid < TI) {
        float s = sred[tid] + sred[tid+64] + sred[tid+128] + sred[tid+192];
        s_sh[tid] = (iBase + tid < hw) ? s : -1e30f;
    }
    __syncthreads();
    if (tid < 32) {
        float m = fmaxf(s_sh[tid], s_sh[tid+32]);
        #pragma unroll
        for (int o = 16; o; o >>= 1) m = fmaxf(m, __shfl_xor_sync(0xffffffffu, m, o));
        if (tid == 0) red_m = m;
    }
    __syncthreads();
    if (tid < TI) p_sh[tid] = expf(s_sh[tid] - red_m);   // invalid -> exp(-1e30) = 0
    __syncthreads();
    if (tid < 32) {
        float z = p_sh[tid] + p_sh[tid+32];
        #pragma unroll
        for (int o = 16; o; o >>= 1) z += __shfl_xor_sync(0xffffffffu, z, o);
        if (tid == 0) red_z = z;
    }
    __syncthreads();

    float* pp = g_part + (size_t)(((size_t)stage*BT + b)*MAXBLK + blk) * PSTRIDE;
    if (tid == 0) { pp[0] = red_m; pp[1] = red_z; }

    for (int c = tid; c < C; c += 256) {
        float w = 0.f;
        #pragma unroll
        for (int j = 0; j < TI; j++) w += p_sh[j] * tileF[c*65 + j];  // conflict-free
        pp[2 + c] = w;
    }
}

// ================= K3: merge partials, project, write aout =================
__global__ void k_combine(const float* __restrict__ Wv, const float* __restrict__ Wco,
                          const float* __restrict__ bco, float* __restrict__ out)
{
    int b = blockIdx.x, s = blockIdx.y, tid = threadIdx.x;
    int nblk = c_nblk[s];
    const float* pb = g_part + (size_t)(((size_t)s*BT + b)*MAXBLK) * PSTRIDE;

    __shared__ float esh[MAXBLK];
    __shared__ float wxsh[C];
    __shared__ float cdsh[DH];
    __shared__ float mg_sh, z_sh;

    if (tid == 0) {
        float m = -1e30f;
        for (int k = 0; k < nblk; k++) m = fmaxf(m, pb[(size_t)k*PSTRIDE]);
        mg_sh = m;
    }
    __syncthreads();
    if (tid < nblk) esh[tid] = expf(pb[(size_t)tid*PSTRIDE] - mg_sh);
    __syncthreads();
    if (tid == 0) {
        float z = 0.f;
        for (int k = 0; k < nblk; k++) z += pb[(size_t)k*PSTRIDE + 1] * esh[k];
        z_sh = z;
    }
    __syncthreads();

    float inv = 1.f / z_sh;
    {
        float wx = 0.f;
        for (int k = 0; k < nblk; k++) wx += esh[k] * pb[(size_t)k*PSTRIDE + 2 + tid];
        wxsh[tid] = wx * inv;
    }
    __syncthreads();

    if (tid < DH) {
        const float* w = Wv + ((size_t)s*DH + tid)*C;
        float d = 0.f;
        #pragma unroll 8
        for (int c = 0; c < C; c++) d += w[c] * wxsh[c];
        cdsh[tid] = d;
    }
    __syncthreads();

    float o = bco[s*C + tid];
    const float* w = Wco + ((size_t)s*C + tid)*DH;
    #pragma unroll
    for (int d = 0; d < DH; d++) o += w[d] * cdsh[d];
    // aout base = total vout elements = 10*384*8500
    out[(size_t)32640000 + (size_t)s*BT*C + (size_t)b*C + tid] = o;
}

// ================= K4: broadcast-fill vout (pure write BW) =================
__global__ void k_fill(float* __restrict__ out, int hw4, int stage)
{
    int row = blockIdx.y;                      // b*384 + c
    int idx = blockIdx.x * blockDim.x + threadIdx.x;
    if (idx >= hw4) return;
    float v = g_outvec[(size_t)stage*BT*C + row];
    ((float4*)out)[(size_t)row*hw4 + idx] = make_float4(v, v, v, v);
}

// ================= launch =================
extern "C" void kernel_launch(void* const* d_in, const int* in_sizes, int n_in,
                              void* d_out, int out_size)
{
    const float *fm[4], *ps[4], *au[4];
    // Dict-insertion order (fmap0,pos0,audio0,...) has in_sizes[1]==in_sizes[0];
    // signature order (fmap0..3, audio0..3, pos0..3) does not.
    bool interleaved = (in_sizes[1] == in_sizes[0]);
    for (int i = 0; i < 4; i++) {
        if (interleaved) {
            fm[i] = (const float*)d_in[3*i];
            ps[i] = (const float*)d_in[3*i + 1];
            au[i] = (const float*)d_in[3*i + 2];
        } else {
            fm[i] = (const float*)d_in[i];
            au[i] = (const float*)d_in[4 + i];
            ps[i] = (const float*)d_in[8 + i];
        }
    }
    const float* Wp  = (const float*)d_in[12];
    const float* bp  = (const float*)d_in[13];
    const float* pe  = (const float*)d_in[14];
    const float* Wqk = (const float*)d_in[15];
    const float* Wcqk= (const float*)d_in[16];
    const float* Wv  = (const float*)d_in[17];
    const float* Wcv = (const float*)d_in[18];
    const float* Wo  = (const float*)d_in[19];
    const float* bo  = (const float*)d_in[20];
    const float* Wco = (const float*)d_in[21];
    const float* bco = (const float*)d_in[22];
    float* out = (float*)d_out;

    static const int    hw[4]   = {6400, 1600, 400, 100};
    static const int    nblk[4] = {100, 25, 7, 2};
    static const size_t voff[4] = {0, 24576000, 30720000, 32256000};

    cudaFuncSetAttribute(k_attn, cudaFuncAttributeMaxDynamicSharedMemorySize, C*65*4);

    k_prep<<<dim3(BT, NS), C>>>(au[0], au[1], au[2], au[3],
                                Wp, bp, pe, Wqk, Wcqk, Wcv, Wo, bo);

    for (int s = 0; s < 4; s++)
        k_attn<<<dim3(nblk[s], BT), 256, C*65*4>>>(fm[s], ps[s], hw[s], s);

    k_combine<<<dim3(BT, NS), C>>>(Wv, Wco, bco, out);

    for (int s = 0; s < 4; s++) {
        int h4 = hw[s] / 4;
        dim3 g((h4 + 255) / 256, BT * C);
        k_fill<<<g, 256>>>(out + voff[s], h4, s);
    }
}

// round 2
// speedup vs baseline: 1.1674x; 1.1674x over previous
#include <cuda_runtime.h>
#include <math.h>

// ---------------- problem constants ----------------
#define NS   4
#define BT   10      // B*T = 2*5
#define C    384
#define CTXC 128
#define DH   64
#define TI   32      // tokens per attn tile
#define MAXBLK 200   // max token-tiles per (stage,b)  (stage0: 6400/32)
#define PSTRIDE 386  // per-partial: m, Z, wx[384]
#define SCALE 0.125f // 64^-0.5

// flattened tile boundaries: s0:2000, s1:500, s2:130, s3:40  -> 2670 total
#define TB0 2000
#define TB1 2500
#define TB2 2630
#define NTILES 2670

// ---------------- scratch (static device globals, allowed) ----------------
__device__ float g_wsim  [NS*BT*C];
__device__ float g_outvec[NS*BT*C];
__device__ float g_part  [NS*BT*MAXBLK*PSTRIDE];   // ~12.4 MB

__constant__ int c_nblk[NS] = {200, 50, 13, 4};

// ================= K1: per-(stage,b) tiny projections =================
__global__ void k_prep(const float* __restrict__ a0, const float* __restrict__ a1,
                       const float* __restrict__ a2, const float* __restrict__ a3,
                       const float* __restrict__ Wp, const float* __restrict__ bp,
                       const float* __restrict__ pe,
                       const float* __restrict__ Wqk, const float* __restrict__ Wcqk,
                       const float* __restrict__ Wcv,
                       const float* __restrict__ Wo,  const float* __restrict__ bo)
{
    int b = blockIdx.x, s = blockIdx.y, tid = threadIdx.x;
    __shared__ float ash[CTXC];
    __shared__ float a_sh[C], apc_sh[C];
    __shared__ float cqk_sh[DH], cv_sh[DH];

    const float* au = (s==0 ? a0 : s==1 ? a1 : s==2 ? a2 : a3) + b*CTXC;
    if (tid < CTXC) ash[tid] = au[tid];
    __syncthreads();

    {
        const float* w = Wp + ((size_t)s*C + tid)*CTXC;
        float acc = bp[s*C + tid];
        #pragma unroll 8
        for (int k = 0; k < CTXC; k++) acc += w[k]*ash[k];
        a_sh[tid]   = acc;
        apc_sh[tid] = acc + pe[((size_t)s*5 + (b%5))*C + tid];
    }
    __syncthreads();

    if (tid < DH) {
        const float* w1 = Wcqk + ((size_t)s*DH + tid)*C;
        const float* w2 = Wcv  + ((size_t)s*DH + tid)*C;
        float q = 0.f, v = 0.f;
        #pragma unroll 8
        for (int c = 0; c < C; c++) { q += w1[c]*apc_sh[c]; v += w2[c]*a_sh[c]; }
        cqk_sh[tid] = q; cv_sh[tid] = v;
    }
    __syncthreads();

    float ws = 0.f;
    float ov = bo[s*C + tid];
    #pragma unroll
    for (int d = 0; d < DH; d++) {
        ws += Wqk[((size_t)s*DH + d)*C + tid] * cqk_sh[d];   // coalesced over tid
        ov += Wo [((size_t)s*C + tid)*DH + d] * cv_sh[d];
    }
    g_wsim  [((size_t)s*BT + b)*C + tid] = ws * SCALE;
    g_outvec[((size_t)s*BT + b)*C + tid] = ov;
}

// ================= K2: fused all-stage streaming attn partials =================
// One block = one 32-token tile of one (stage,b). 512 threads = 16 channel
// groups x 32 tokens. Each thread streams 24 channels (c = g + 16*k),
// caching fmap in padded smem (stride 33), and accumulates sim partial.
// Then block-local softmax over 32 tokens + weighted fmap sum -> partial.
extern __shared__ float tileF[];   // C * 33 floats = 50,688 B

__global__ __launch_bounds__(512) void k_attn(
        const float* __restrict__ f0, const float* __restrict__ f1,
        const float* __restrict__ f2, const float* __restrict__ f3,
        const float* __restrict__ p0, const float* __restrict__ p1,
        const float* __restrict__ p2, const float* __restrict__ p3)
{
    __shared__ float wsh[C];
    __shared__ float sred[512];
    __shared__ float p_sh[TI];
    __shared__ float red_m, red_z;

    int t = blockIdx.x;
    int stage, hw, perB, tbase;
    const float *fmap, *pos;
    if (t < TB0)      { stage=0; hw=6400; perB=200; tbase=0;   fmap=f0; pos=p0; }
    else if (t < TB1) { stage=1; hw=1600; perB=50;  tbase=TB0; fmap=f1; pos=p1; }
    else if (t < TB2) { stage=2; hw=400;  perB=13;  tbase=TB1; fmap=f2; pos=p2; }
    else              { stage=3; hw=100;  perB=4;   tbase=TB2; fmap=f3; pos=p3; }
    int r   = t - tbase;
    int b   = r / perB;
    int blk = r % perB;

    int tid = threadIdx.x;
    int g   = tid >> 5;        // 0..15 channel group
    int j   = tid & 31;        // token within tile
    int iBase = blk * TI;
    int token = iBase + j;
    bool valid = token < hw;

    for (int c = tid; c < C; c += 512)
        wsh[c] = g_wsim[((size_t)stage*BT + b)*C + c];
    __syncthreads();

    float acc = 0.f;
    if (valid) {
        const float* fb = fmap + (size_t)b*C*hw + token;
        const float* pb = pos  + (size_t)b*C*hw + token;
        #pragma unroll 8
        for (int k = 0; k < 24; k++) {
            int c = g + (k << 4);
            size_t off = (size_t)c * hw;
            float f = __ldg(fb + off);
            float p = __ldg(pb + off);
            tileF[c*33 + j] = f;
            acc += (f + p) * wsh[c];
        }
    } else {
        #pragma unroll 8
        for (int k = 0; k < 24; k++) tileF[(g + (k<<4))*33 + j] = 0.f;
    }
    sred[tid] = acc;
    __syncthreads();

    // single warp: finish s_j, softmax over 32 tokens
    if (tid < 32) {
        float s = 0.f;
        #pragma unroll
        for (int gg = 0; gg < 16; gg++) s += sred[gg*32 + tid];
        if (iBase + tid >= hw) s = -1e30f;
        float m = s;
        #pragma unroll
        for (int o = 16; o; o >>= 1) m = fmaxf(m, __shfl_xor_sync(0xffffffffu, m, o));
        float e = expf(s - m);
        p_sh[tid] = e;
        float z = e;
        #pragma unroll
        for (int o = 16; o; o >>= 1) z += __shfl_xor_sync(0xffffffffu, z, o);
        if (tid == 0) { red_m = m; red_z = z; }
    }
    __syncthreads();

    float* pp = g_part + (size_t)(((size_t)stage*BT + b)*MAXBLK + blk) * PSTRIDE;
    if (tid == 0) { pp[0] = red_m; pp[1] = red_z; }

    for (int c = tid; c < C; c += 512) {
        float w = 0.f;
        #pragma unroll
        for (int jj = 0; jj < TI; jj++) w += p_sh[jj] * tileF[c*33 + jj];
        pp[2 + c] = w;
    }
}

// ================= K3: merge partials, project, write aout =================
__global__ void k_combine(const float* __restrict__ Wv, const float* __restrict__ Wco,
                          const float* __restrict__ bco, float* __restrict__ out)
{
    int b = blockIdx.x, s = blockIdx.y, tid = threadIdx.x;
    int nblk = c_nblk[s];
    const float* pb = g_part + (size_t)(((size_t)s*BT + b)*MAXBLK) * PSTRIDE;

    __shared__ float msh[MAXBLK], zsh[MAXBLK], esh[MAXBLK];
    __shared__ float wxsh[C];
    __shared__ float cdsh[DH];
    __shared__ float mg_sh, z_sh;

    if (tid < nblk) {
        msh[tid] = pb[(size_t)tid*PSTRIDE];
        zsh[tid] = pb[(size_t)tid*PSTRIDE + 1];
    }
    __syncthreads();
    if (tid == 0) {
        float m = -1e30f;
        for (int k = 0; k < nblk; k++) m = fmaxf(m, msh[k]);
        mg_sh = m;
    }
    __syncthreads();
    if (tid < nblk) esh[tid] = expf(msh[tid] - mg_sh);
    __syncthreads();
    if (tid == 0) {
        float z = 0.f;
        for (int k = 0; k < nblk; k++) z += zsh[k] * esh[k];
        z_sh = z;
    }
    __syncthreads();

    float inv = 1.f / z_sh;
    {
        float wx = 0.f;
        for (int k = 0; k < nblk; k++) wx += esh[k] * pb[(size_t)k*PSTRIDE + 2 + tid];
        wxsh[tid] = wx * inv;
    }
    __syncthreads();

    if (tid < DH) {
        const float* w = Wv + ((size_t)s*DH + tid)*C;
        float d = 0.f;
        #pragma unroll 8
        for (int c = 0; c < C; c++) d += w[c] * wxsh[c];
        cdsh[tid] = d;
    }
    __syncthreads();

    float o = bco[s*C + tid];
    const float* w = Wco + ((size_t)s*C + tid)*DH;
    #pragma unroll
    for (int d = 0; d < DH; d++) o += w[d] * cdsh[d];
    out[(size_t)32640000 + (size_t)s*BT*C + (size_t)b*C + tid] = o;
}

// ================= K4: fused broadcast-fill of all vout (pure write BW) =================
// out4[g] = outvec[stage*3840 + row(g)], stage from float4-boundaries.
__global__ __launch_bounds__(256) void k_fill(float4* __restrict__ out4)
{
    long long g = (long long)blockIdx.x * 256 + threadIdx.x;
    if (g >= 8160000LL) return;
    int row;
    if (g < 6144000LL) {               // stage 0, h4=1600
        row = (int)(g / 1600);
    } else if (g < 7680000LL) {        // stage 1, h4=400
        row = 3840 + (int)((g - 6144000LL) / 400);
    } else if (g < 8064000LL) {        // stage 2, h4=100
        row = 7680 + (int)((g - 7680000LL) / 100);
    } else {                           // stage 3, h4=25
        row = 11520 + (int)((g - 8064000LL) / 25);
    }
    float v = __ldg(&g_outvec[row]);
    out4[g] = make_float4(v, v, v, v);
}

// ================= launch =================
extern "C" void kernel_launch(void* const* d_in, const int* in_sizes, int n_in,
                              void* d_out, int out_size)
{
    const float *fm[4], *ps[4], *au[4];
    bool interleaved = (in_sizes[1] == in_sizes[0]);
    for (int i = 0; i < 4; i++) {
        if (interleaved) {
            fm[i] = (const float*)d_in[3*i];
            ps[i] = (const float*)d_in[3*i + 1];
            au[i] = (const float*)d_in[3*i + 2];
        } else {
            fm[i] = (const float*)d_in[i];
            au[i] = (const float*)d_in[4 + i];
            ps[i] = (const float*)d_in[8 + i];
        }
    }
    const float* Wp  = (const float*)d_in[12];
    const float* bp  = (const float*)d_in[13];
    const float* pe  = (const float*)d_in[14];
    const float* Wqk = (const float*)d_in[15];
    const float* Wcqk= (const float*)d_in[16];
    const float* Wv  = (const float*)d_in[17];
    const float* Wcv = (const float*)d_in[18];
    const float* Wo  = (const float*)d_in[19];
    const float* bo  = (const float*)d_in[20];
    const float* Wco = (const float*)d_in[21];
    const float* bco = (const float*)d_in[22];
    float* out = (float*)d_out;

    cudaFuncSetAttribute(k_attn, cudaFuncAttributeMaxDynamicSharedMemorySize, C*33*4);

    k_prep<<<dim3(BT, NS), C>>>(au[0], au[1], au[2], au[3],
                                Wp, bp, pe, Wqk, Wcqk, Wcv, Wo, bo);

    k_attn<<<NTILES, 512, C*33*4>>>(fm[0], fm[1], fm[2], fm[3],
                                    ps[0], ps[1], ps[2], ps[3]);

    k_combine<<<dim3(BT, NS), C>>>(Wv, Wco, bco, out);

    k_fill<<<(8160000 + 255)/256, 256>>>((float4*)out);
}

// round 3
// speedup vs baseline: 1.3446x; 1.1518x over previous
#include <cuda_runtime.h>
#include <math.h>

// ---------------- problem constants ----------------
#define NS   4
#define BT   10      // B*T = 2*5
#define C    384
#define CTXC 128
#define DH   64
#define TI   32      // tokens per attn tile
#define MAXBLK 200   // max token-tiles per (stage,b)  (stage0: 6400/32)
#define PSTRIDE 386  // per-partial: m, Z, wx[384]
#define SCALE 0.125f

// flattened attn tile boundaries: s0:2000, s1:500, s2:130, s3:40 -> 2670
#define TB0 2000
#define TB1 2500
#define TB2 2630
#define NTILES 2670

// fill: 8,160,000 float4s, 2048 per fill-block -> 3985 needed (4005 launched)
#define NF4 8160000
#define NGROUPS 1335    // grid = 1335*5; each group: 2 attn + 3 fill blocks

// ---------------- scratch ----------------
__device__ float g_wsim  [NS*BT*C];
__device__ float g_outvec[NS*BT*C];
__device__ float g_part  [NS*BT*MAXBLK*PSTRIDE];   // ~12.4 MB

__constant__ int c_nblk[NS] = {200, 50, 13, 4};

// ================= K1: per-(stage,b) tiny projections =================
__global__ void k_prep(const float* __restrict__ a0, const float* __restrict__ a1,
                       const float* __restrict__ a2, const float* __restrict__ a3,
                       const float* __restrict__ Wp, const float* __restrict__ bp,
                       const float* __restrict__ pe,
                       const float* __restrict__ Wqk, const float* __restrict__ Wcqk,
                       const float* __restrict__ Wcv,
                       const float* __restrict__ Wo,  const float* __restrict__ bo)
{
    int b = blockIdx.x, s = blockIdx.y, tid = threadIdx.x;
    __shared__ float ash[CTXC];
    __shared__ float a_sh[C], apc_sh[C];
    __shared__ float cqk_sh[DH], cv_sh[DH];

    const float* au = (s==0 ? a0 : s==1 ? a1 : s==2 ? a2 : a3) + b*CTXC;
    if (tid < CTXC) ash[tid] = au[tid];
    __syncthreads();

    {
        const float* w = Wp + ((size_t)s*C + tid)*CTXC;
        float acc = bp[s*C + tid];
        #pragma unroll 8
        for (int k = 0; k < CTXC; k++) acc += w[k]*ash[k];
        a_sh[tid]   = acc;
        apc_sh[tid] = acc + pe[((size_t)s*5 + (b%5))*C + tid];
    }
    __syncthreads();

    if (tid < DH) {
        const float* w1 = Wcqk + ((size_t)s*DH + tid)*C;
        const float* w2 = Wcv  + ((size_t)s*DH + tid)*C;
        float q = 0.f, v = 0.f;
        #pragma unroll 8
        for (int c = 0; c < C; c++) { q += w1[c]*apc_sh[c]; v += w2[c]*a_sh[c]; }
        cqk_sh[tid] = q; cv_sh[tid] = v;
    }
    __syncthreads();

    float ws = 0.f;
    float ov = bo[s*C + tid];
    #pragma unroll
    for (int d = 0; d < DH; d++) {
        ws += Wqk[((size_t)s*DH + d)*C + tid] * cqk_sh[d];
        ov += Wo [((size_t)s*C + tid)*DH + d] * cv_sh[d];
    }
    g_wsim  [((size_t)s*BT + b)*C + tid] = ws * SCALE;
    g_outvec[((size_t)s*BT + b)*C + tid] = ov;
}

// ================= K2: fused attn-partials + vout broadcast-fill =================
// Grid groups of 5 blocks: 2 attn-tile blocks + 3 fill blocks (interleaved so
// read-heavy and write-heavy traffic share HBM throughout the kernel).
//
// Attn tile block: 512 threads = 64 channel-groups x 8 token-quads.
// Thread (g, j4) float4-loads f,p for channels c = g+64k (k<6) at tokens
// j4*4..j4*4+3, keeps f in registers across the softmax barrier, then
// computes per-channel weighted sums via width-8 shfl reduction. No fmap
// tile in smem at all (~10 KB static smem, 2 CTAs/SM via launch_bounds).
__global__ __launch_bounds__(512, 2) void k_main(
        const float* __restrict__ f0, const float* __restrict__ f1,
        const float* __restrict__ f2, const float* __restrict__ f3,
        const float* __restrict__ p0, const float* __restrict__ p1,
        const float* __restrict__ p2, const float* __restrict__ p3,
        float4* __restrict__ out4)
{
    __shared__ float wsh[C];
    __shared__ float sred[64*33];
    __shared__ float p_sh[TI];

    int grp = blockIdx.x / 5, lane5 = blockIdx.x % 5;
    int tid = threadIdx.x;

    if (lane5 >= 2) {
        // ---------- fill block ----------
        int fb = grp*3 + (lane5 - 2);
        int base = fb * 2048 + tid;
        #pragma unroll
        for (int k = 0; k < 4; k++) {
            int idx = base + k*512;
            if (idx < NF4) {
                int row;
                if (idx < 6144000)      row = idx / 1600;
                else if (idx < 7680000) row = 3840  + (idx - 6144000) / 400;
                else if (idx < 8064000) row = 7680  + (idx - 7680000) / 100;
                else                    row = 11520 + (idx - 8064000) / 25;
                float v = __ldg(&g_outvec[row]);
                out4[idx] = make_float4(v, v, v, v);
            }
        }
        return;
    }

    // ---------- attn tile block ----------
    int t = grp*2 + lane5;
    int stage, hw, b, blk;
    const float *fmap, *pos;
    if (t < TB0)      { stage=0; hw=6400; b=t/200;          blk=t%200;          fmap=f0; pos=p0; }
    else if (t < TB1) { stage=1; hw=1600; b=(t-TB0)/50;     blk=(t-TB0)%50;     fmap=f1; pos=p1; }
    else if (t < TB2) { stage=2; hw=400;  b=(t-TB1)/13;     blk=(t-TB1)%13;     fmap=f2; pos=p2; }
    else              { stage=3; hw=100;  b=(t-TB2)/4;      blk=(t-TB2)%4;      fmap=f3; pos=p3; }

    int g   = tid >> 3;        // 0..63 channel group
    int j4  = tid & 7;         // token quad
    int iBase = blk * TI;
    int tok0  = iBase + j4*4;
    bool valid = tok0 < hw;    // hw % 4 == 0, tok0 % 4 == 0 -> full quad valid

    if (tid < C) wsh[tid] = g_wsim[((size_t)stage*BT + b)*C + tid];
    __syncthreads();

    float4 fc[6];
    float a0 = 0.f, a1 = 0.f, a2 = 0.f, a3 = 0.f;
    if (valid) {
        const float* fbp = fmap + (size_t)b*C*hw + tok0;
        const float* pbp = pos  + (size_t)b*C*hw + tok0;
        #pragma unroll
        for (int k = 0; k < 6; k++) {
            int c = g + (k << 6);
            size_t off = (size_t)c * hw;
            float4 f4 = *(const float4*)(fbp + off);
            float4 p4 = *(const float4*)(pbp + off);
            fc[k] = f4;
            float w = wsh[c];
            a0 += (f4.x + p4.x) * w;
            a1 += (f4.y + p4.y) * w;
            a2 += (f4.z + p4.z) * w;
            a3 += (f4.w + p4.w) * w;
        }
    } else {
        #pragma unroll
        for (int k = 0; k < 6; k++) fc[k] = make_float4(0.f,0.f,0.f,0.f);
    }
    // sred[g][token], stride 33: lane bank = (g + 4*j4) % 32 -> permutation, conflict-free
    {
        float* sr = sred + g*33 + j4*4;
        sr[0] = a0; sr[1] = a1; sr[2] = a2; sr[3] = a3;
    }
    __syncthreads();

    float* pp = g_part + (size_t)(((size_t)stage*BT + b)*MAXBLK + blk) * PSTRIDE;

    if (tid < 32) {
        float s = 0.f;
        #pragma unroll 8
        for (int gg = 0; gg < 64; gg++) s += sred[gg*33 + tid];
        if (iBase + tid >= hw) s = -1e30f;
        float m = s;
        #pragma unroll
        for (int o = 16; o; o >>= 1) m = fmaxf(m, __shfl_xor_sync(0xffffffffu, m, o));
        float e = expf(s - m);
        p_sh[tid] = e;
        float z = e;
        #pragma unroll
        for (int o = 16; o; o >>= 1) z += __shfl_xor_sync(0xffffffffu, z, o);
        if (tid == 0) { pp[0] = m; pp[1] = z; }
    }
    __syncthreads();

    float q0 = p_sh[j4*4 + 0], q1 = p_sh[j4*4 + 1];
    float q2 = p_sh[j4*4 + 2], q3 = p_sh[j4*4 + 3];
    #pragma unroll
    for (int k = 0; k < 6; k++) {
        float w = fc[k].x*q0 + fc[k].y*q1 + fc[k].z*q2 + fc[k].w*q3;
        w += __shfl_xor_sync(0xffffffffu, w, 1, 8);
        w += __shfl_xor_sync(0xffffffffu, w, 2, 8);
        w += __shfl_xor_sync(0xffffffffu, w, 4, 8);
        if (j4 == 0) pp[2 + g + (k << 6)] = w;
    }
}

// ================= K3: merge partials, project, write aout =================
__global__ void k_combine(const float* __restrict__ Wv, const float* __restrict__ Wco,
                          const float* __restrict__ bco, float* __restrict__ out)
{
    int b = blockIdx.x, s = blockIdx.y, tid = threadIdx.x;
    int nblk = c_nblk[s];
    const float* pb = g_part + (size_t)(((size_t)s*BT + b)*MAXBLK) * PSTRIDE;

    __shared__ float msh[MAXBLK], zsh[MAXBLK], esh[MAXBLK];
    __shared__ float wxsh[C];
    __shared__ float cdsh[DH];
    __shared__ float mg_sh, z_sh;

    if (tid < nblk) {
        msh[tid] = pb[(size_t)tid*PSTRIDE];
        zsh[tid] = pb[(size_t)tid*PSTRIDE + 1];
    }
    __syncthreads();
    if (tid == 0) {
        float m = -1e30f;
        for (int k = 0; k < nblk; k++) m = fmaxf(m, msh[k]);
        mg_sh = m;
    }
    __syncthreads();
    if (tid < nblk) esh[tid] = expf(msh[tid] - mg_sh);
    __syncthreads();
    if (tid == 0) {
        float z = 0.f;
        for (int k = 0; k < nblk; k++) z += zsh[k] * esh[k];
        z_sh = z;
    }
    __syncthreads();

    float inv = 1.f / z_sh;
    {
        float wx = 0.f;
        for (int k = 0; k < nblk; k++) wx += esh[k] * pb[(size_t)k*PSTRIDE + 2 + tid];
        wxsh[tid] = wx * inv;
    }
    __syncthreads();

    if (tid < DH) {
        const float* w = Wv + ((size_t)s*DH + tid)*C;
        float d = 0.f;
        #pragma unroll 8
        for (int c = 0; c < C; c++) d += w[c] * wxsh[c];
        cdsh[tid] = d;
    }
    __syncthreads();

    float o = bco[s*C + tid];
    const float* w = Wco + ((size_t)s*C + tid)*DH;
    #pragma unroll
    for (int d = 0; d < DH; d++) o += w[d] * cdsh[d];
    out[(size_t)32640000 + (size_t)s*BT*C + (size_t)b*C + tid] = o;
}

// ================= launch =================
extern "C" void kernel_launch(void* const* d_in, const int* in_sizes, int n_in,
                              void* d_out, int out_size)
{
    const float *fm[4], *ps[4], *au[4];
    bool interleaved = (in_sizes[1] == in_sizes[0]);
    for (int i = 0; i < 4; i++) {
        if (interleaved) {
            fm[i] = (const float*)d_in[3*i];
            ps[i] = (const float*)d_in[3*i + 1];
            au[i] = (const float*)d_in[3*i + 2];
        } else {
            fm[i] = (const float*)d_in[i];
            au[i] = (const float*)d_in[4 + i];
            ps[i] = (const float*)d_in[8 + i];
        }
    }
    const float* Wp  = (const float*)d_in[12];
    const float* bp  = (const float*)d_in[13];
    const float* pe  = (const float*)d_in[14];
    const float* Wqk = (const float*)d_in[15];
    const float* Wcqk= (const float*)d_in[16];
    const float* Wv  = (const float*)d_in[17];
    const float* Wcv = (const float*)d_in[18];
    const float* Wo  = (const float*)d_in[19];
    const float* bo  = (const float*)d_in[20];
    const float* Wco = (const float*)d_in[21];
    const float* bco = (const float*)d_in[22];
    float* out = (float*)d_out;

    k_prep<<<dim3(BT, NS), C>>>(au[0], au[1], au[2], au[3],
                                Wp, bp, pe, Wqk, Wcqk, Wcv, Wo, bo);

    k_main<<<NGROUPS*5, 512>>>(fm[0], fm[1], fm[2], fm[3],
                               ps[0], ps[1], ps[2], ps[3],
                               (float4*)out);

    k_combine<<<dim3(BT, NS), C>>>(Wv, Wco, bco, out);
}

// round 4
// speedup vs baseline: 2.4446x; 1.8181x over previous
#include <cuda_runtime.h>
#include <math.h>

// ---------------- problem constants ----------------
#define NS   4
#define BT   10
#define C    384
#define CTXC 128
#define DH   64
#define TI   32
#define MAXBLK 200
#define PSTRIDE 386
#define SCALE 0.125f

#define TB0 2000
#define TB1 2500
#define TB2 2630
#define NTILES 2670

#define NF4 8160000
#define NGROUPS 1335

// ---------------- scratch ----------------
__device__ float g_wsim  [NS*BT*C];
__device__ float g_outvec[NS*BT*C];
__device__ float g_part  [NS*BT*MAXBLK*PSTRIDE];

__constant__ int c_nblk[NS] = {200, 50, 13, 4};

// ================= K1: per-(stage,b) tiny projections, MLP-optimized =================
__global__ __launch_bounds__(384) void k_prep(
                       const float* __restrict__ a0, const float* __restrict__ a1,
                       const float* __restrict__ a2, const float* __restrict__ a3,
                       const float* __restrict__ Wp, const float* __restrict__ bp,
                       const float* __restrict__ pe,
                       const float* __restrict__ Wqk, const float* __restrict__ Wcqk,
                       const float* __restrict__ Wcv,
                       const float* __restrict__ Wo,  const float* __restrict__ bo)
{
    int b = blockIdx.x, s = blockIdx.y, tid = threadIdx.x;
    __shared__ float ash[CTXC];
    __shared__ float a_sh[C], apc_sh[C];
    __shared__ float psh[6][DH];
    __shared__ float cqk_sh[DH], cv_sh[DH];

    const float* au = (s==0 ? a0 : s==1 ? a1 : s==2 ? a2 : a3) + b*CTXC;
    if (tid < CTXC) ash[tid] = au[tid];
    __syncthreads();

    // ---- a = Wp @ audio + bp : one output per thread, 32 float4 loads in flight
    {
        const float4* w = (const float4*)(Wp + ((size_t)s*C + tid)*CTXC);
        float acc = bp[s*C + tid];
        #pragma unroll
        for (int k = 0; k < 32; k++) {
            float4 w4 = __ldg(&w[k]);
            acc += w4.x*ash[4*k] + w4.y*ash[4*k+1] + w4.z*ash[4*k+2] + w4.w*ash[4*k+3];
        }
        a_sh[tid]   = acc;
        apc_sh[tid] = acc + pe[((size_t)s*5 + (b%5))*C + tid];
    }
    __syncthreads();

    // ---- cqk = Wcqk @ apc, cv = Wcv @ a : 384 threads = 2 mats x 3 segs x 64 outs
    {
        int o   = tid & 63;
        int grpI= tid >> 6;        // 0..5
        int mat = grpI & 1;        // 0 = cqk, 1 = cv
        int seg = grpI >> 1;       // 0..2 (128 channels each)
        const float* W = mat ? Wcv : Wcqk;
        const float* x = (mat ? a_sh : apc_sh) + seg*128;
        const float4* w = (const float4*)(W + ((size_t)s*DH + o)*C + seg*128);
        float acc = 0.f;
        #pragma unroll
        for (int k = 0; k < 32; k++) {
            float4 w4 = __ldg(&w[k]);
            acc += w4.x*x[4*k] + w4.y*x[4*k+1] + w4.z*x[4*k+2] + w4.w*x[4*k+3];
        }
        psh[grpI][o] = acc;
    }
    __syncthreads();
    if (tid < 128) {
        int mat = tid >> 6, o = tid & 63;
        float v = psh[mat][o] + psh[mat+2][o] + psh[mat+4][o];
        if (mat == 0) cqk_sh[o] = v; else cv_sh[o] = v;
    }
    __syncthreads();

    // ---- wsim = SCALE * Wqk^T cqk (coalesced over tid), outvec = Wo cv + bo (float4)
    float ws = 0.f;
    #pragma unroll
    for (int d = 0; d < DH; d++)
        ws += __ldg(&Wqk[((size_t)s*DH + d)*C + tid]) * cqk_sh[d];

    float ov = bo[s*C + tid];
    {
        const float4* w = (const float4*)(Wo + ((size_t)s*C + tid)*DH);
        #pragma unroll
        for (int k = 0; k < 16; k++) {
            float4 w4 = __ldg(&w[k]);
            ov += w4.x*cv_sh[4*k] + w4.y*cv_sh[4*k+1] + w4.z*cv_sh[4*k+2] + w4.w*cv_sh[4*k+3];
        }
    }
    g_wsim  [((size_t)s*BT + b)*C + tid] = ws * SCALE;
    g_outvec[((size_t)s*BT + b)*C + tid] = ov;
}

// ================= K2: fused attn-partials + vout broadcast-fill =================
__global__ __launch_bounds__(512, 2) void k_main(
        const float* __restrict__ f0, const float* __restrict__ f1,
        const float* __restrict__ f2, const float* __restrict__ f3,
        const float* __restrict__ p0, const float* __restrict__ p1,
        const float* __restrict__ p2, const float* __restrict__ p3,
        float4* __restrict__ out4)
{
    __shared__ float wsh[C];
    __shared__ float sred[64*33];
    __shared__ float p_sh[TI];

    int grp = blockIdx.x / 5, lane5 = blockIdx.x % 5;
    int tid = threadIdx.x;

    if (lane5 >= 2) {
        // ---------- fill block ----------
        int fb = grp*3 + (lane5 - 2);
        int base = fb * 2048 + tid;
        #pragma unroll
        for (int k = 0; k < 4; k++) {
            int idx = base + k*512;
            if (idx < NF4) {
                int row;
                if (idx < 6144000)      row = idx / 1600;
                else if (idx < 7680000) row = 3840  + (idx - 6144000) / 400;
                else if (idx < 8064000) row = 7680  + (idx - 7680000) / 100;
                else                    row = 11520 + (idx - 8064000) / 25;
                float v = __ldg(&g_outvec[row]);
                out4[idx] = make_float4(v, v, v, v);
            }
        }
        return;
    }

    // ---------- attn tile block ----------
    int t = grp*2 + lane5;
    int stage, hw, b, blk;
    const float *fmap, *pos;
    if (t < TB0)      { stage=0; hw=6400; b=t/200;      blk=t%200;      fmap=f0; pos=p0; }
    else if (t < TB1) { stage=1; hw=1600; b=(t-TB0)/50; blk=(t-TB0)%50; fmap=f1; pos=p1; }
    else if (t < TB2) { stage=2; hw=400;  b=(t-TB1)/13; blk=(t-TB1)%13; fmap=f2; pos=p2; }
    else              { stage=3; hw=100;  b=(t-TB2)/4;  blk=(t-TB2)%4;  fmap=f3; pos=p3; }

    int g   = tid >> 3;
    int j4  = tid & 7;
    int iBase = blk * TI;
    int tok0  = iBase + j4*4;
    bool valid = tok0 < hw;

    if (tid < C) wsh[tid] = g_wsim[((size_t)stage*BT + b)*C + tid];
    __syncthreads();

    float4 fc[6];
    float a0 = 0.f, a1 = 0.f, a2 = 0.f, a3 = 0.f;
    if (valid) {
        const float* fbp = fmap + (size_t)b*C*hw + tok0;
        const float* pbp = pos  + (size_t)b*C*hw + tok0;
        #pragma unroll
        for (int k = 0; k < 6; k++) {
            int c = g + (k << 6);
            size_t off = (size_t)c * hw;
            float4 f4 = *(const float4*)(fbp + off);
            float4 p4 = *(const float4*)(pbp + off);
            fc[k] = f4;
            float w = wsh[c];
            a0 += (f4.x + p4.x) * w;
            a1 += (f4.y + p4.y) * w;
            a2 += (f4.z + p4.z) * w;
            a3 += (f4.w + p4.w) * w;
        }
    } else {
        #pragma unroll
        for (int k = 0; k < 6; k++) fc[k] = make_float4(0.f,0.f,0.f,0.f);
    }
    {
        float* sr = sred + g*33 + j4*4;
        sr[0] = a0; sr[1] = a1; sr[2] = a2; sr[3] = a3;
    }
    __syncthreads();

    float* pp = g_part + (size_t)(((size_t)stage*BT + b)*MAXBLK + blk) * PSTRIDE;

    if (tid < 32) {
        float s = 0.f;
        #pragma unroll 8
        for (int gg = 0; gg < 64; gg++) s += sred[gg*33 + tid];
        if (iBase + tid >= hw) s = -1e30f;
        float m = s;
        #pragma unroll
        for (int o = 16; o; o >>= 1) m = fmaxf(m, __shfl_xor_sync(0xffffffffu, m, o));
        float e = expf(s - m);
        p_sh[tid] = e;
        float z = e;
        #pragma unroll
        for (int o = 16; o; o >>= 1) z += __shfl_xor_sync(0xffffffffu, z, o);
        if (tid == 0) { pp[0] = m; pp[1] = z; }
    }
    __syncthreads();

    float q0 = p_sh[j4*4 + 0], q1 = p_sh[j4*4 + 1];
    float q2 = p_sh[j4*4 + 2], q3 = p_sh[j4*4 + 3];
    #pragma unroll
    for (int k = 0; k < 6; k++) {
        float w = fc[k].x*q0 + fc[k].y*q1 + fc[k].z*q2 + fc[k].w*q3;
        w += __shfl_xor_sync(0xffffffffu, w, 1, 8);
        w += __shfl_xor_sync(0xffffffffu, w, 2, 8);
        w += __shfl_xor_sync(0xffffffffu, w, 4, 8);
        if (j4 == 0) pp[2 + g + (k << 6)] = w;
    }
}

// ================= K3: merge partials, project, write aout =================
__global__ __launch_bounds__(384) void k_combine(
                          const float* __restrict__ Wv, const float* __restrict__ Wco,
                          const float* __restrict__ bco, float* __restrict__ out)
{
    int b = blockIdx.x, s = blockIdx.y, tid = threadIdx.x;
    int nblk = c_nblk[s];
    const float* pb = g_part + (size_t)(((size_t)s*BT + b)*MAXBLK) * PSTRIDE;

    __shared__ float msh[MAXBLK], zsh[MAXBLK], esh[MAXBLK];
    __shared__ float wxsh[C];
    __shared__ float psh2[3][DH];
    __shared__ float cdsh[DH];
    __shared__ float mg_sh, z_sh;

    if (tid < nblk) {
        msh[tid] = pb[(size_t)tid*PSTRIDE];
        zsh[tid] = pb[(size_t)tid*PSTRIDE + 1];
    }
    __syncthreads();
    if (tid == 0) {
        float m = -1e30f;
        for (int k = 0; k < nblk; k++) m = fmaxf(m, msh[k]);
        mg_sh = m;
    }
    __syncthreads();
    if (tid < nblk) esh[tid] = expf(msh[tid] - mg_sh);
    __syncthreads();
    if (tid == 0) {
        float z = 0.f;
        for (int k = 0; k < nblk; k++) z += zsh[k] * esh[k];
        z_sh = z;
    }
    __syncthreads();

    // merge weighted sums; unrolled x8 with independent accumulators for MLP
    float inv = 1.f / z_sh;
    {
        float x0=0.f,x1=0.f,x2=0.f,x3=0.f,x4=0.f,x5=0.f,x6=0.f,x7=0.f;
        const float* p2 = pb + 2 + tid;
        int k = 0;
        for (; k + 8 <= nblk; k += 8) {
            x0 += esh[k  ] * __ldg(p2 + (size_t)(k  )*PSTRIDE);
            x1 += esh[k+1] * __ldg(p2 + (size_t)(k+1)*PSTRIDE);
            x2 += esh[k+2] * __ldg(p2 + (size_t)(k+2)*PSTRIDE);
            x3 += esh[k+3] * __ldg(p2 + (size_t)(k+3)*PSTRIDE);
            x4 += esh[k+4] * __ldg(p2 + (size_t)(k+4)*PSTRIDE);
            x5 += esh[k+5] * __ldg(p2 + (size_t)(k+5)*PSTRIDE);
            x6 += esh[k+6] * __ldg(p2 + (size_t)(k+6)*PSTRIDE);
            x7 += esh[k+7] * __ldg(p2 + (size_t)(k+7)*PSTRIDE);
        }
        for (; k < nblk; k++) x0 += esh[k] * __ldg(p2 + (size_t)k*PSTRIDE);
        wxsh[tid] = ((x0+x1)+(x2+x3)+((x4+x5)+(x6+x7))) * inv;
    }
    __syncthreads();

    // cd = Wv @ wx : 3 segs x 64 outs across 192 threads (float4 loads)
    if (tid < 192) {
        int o = tid & 63, seg = tid >> 6;
        const float4* w = (const float4*)(Wv + ((size_t)s*DH + o)*C + seg*128);
        const float* x = wxsh + seg*128;
        float acc = 0.f;
        #pragma unroll
        for (int k = 0; k < 32; k++) {
            float4 w4 = __ldg(&w[k]);
            acc += w4.x*x[4*k] + w4.y*x[4*k+1] + w4.z*x[4*k+2] + w4.w*x[4*k+3];
        }
        psh2[seg][o] = acc;
    }
    __syncthreads();
    if (tid < DH) cdsh[tid] = psh2[0][tid] + psh2[1][tid] + psh2[2][tid];
    __syncthreads();

    float o = bco[s*C + tid];
    {
        const float4* w = (const float4*)(Wco + ((size_t)s*C + tid)*DH);
        #pragma unroll
        for (int k = 0; k < 16; k++) {
            float4 w4 = __ldg(&w[k]);
            o += w4.x*cdsh[4*k] + w4.y*cdsh[4*k+1] + w4.z*cdsh[4*k+2] + w4.w*cdsh[4*k+3];
        }
    }
    out[(size_t)32640000 + (size_t)s*BT*C + (size_t)b*C + tid] = o;
}

// ================= launch =================
extern "C" void kernel_launch(void* const* d_in, const int* in_sizes, int n_in,
                              void* d_out, int out_size)
{
    const float *fm[4], *ps[4], *au[4];
    bool interleaved = (in_sizes[1] == in_sizes[0]);
    for (int i = 0; i < 4; i++) {
        if (interleaved) {
            fm[i] = (const float*)d_in[3*i];
            ps[i] = (const float*)d_in[3*i + 1];
            au[i] = (const float*)d_in[3*i + 2];
        } else {
            fm[i] = (const float*)d_in[i];
            au[i] = (const float*)d_in[4 + i];
            ps[i] = (const float*)d_in[8 + i];
        }
    }
    const float* Wp  = (const float*)d_in[12];
    const float* bp  = (const float*)d_in[13];
    const float* pe  = (const float*)d_in[14];
    const float* Wqk = (const float*)d_in[15];
    const float* Wcqk= (const float*)d_in[16];
    const float* Wv  = (const float*)d_in[17];
    const float* Wcv = (const float*)d_in[18];
    const float* Wo  = (const float*)d_in[19];
    const float* bo  = (const float*)d_in[20];
    const float* Wco = (const float*)d_in[21];
    const float* bco = (const float*)d_in[22];
    float* out = (float*)d_out;

    k_prep<<<dim3(BT, NS), C>>>(au[0], au[1], au[2], au[3],
                                Wp, bp, pe, Wqk, Wcqk, Wcv, Wo, bo);

    k_main<<<NGROUPS*5, 512>>>(fm[0], fm[1], fm[2], fm[3],
                               ps[0], ps[1], ps[2], ps[3],
                               (float4*)out);

    k_combine<<<dim3(BT, NS), C>>>(Wv, Wco, bco, out);
}